// round 11
// baseline (speedup 1.0000x reference)
#include <cuda_runtime.h>
#include <cuda_bf16.h>

// 3D RoPE apply:
//   x: (1, S, N=16, D=128) fp32, S = f*h*w (= 32760)
//   freqs_cos/sin: (1024, 64) fp32, cols [0,22)=F, [22,43)=H, [43,64)=W
//   seq pos s -> (fi, hi, wi); pair c: row = fi (c<22) | hi (c<43) | wi
//   out pair: (xr*cos - xi*sin, xr*sin + xi*cos)
//
// R10: PERSISTENT kernel. 296 blocks (2 CTA/SM x 148 SMs) grid-stride over
// 8-position chunks. Double-buffered smem tables -> one barrier per
// iteration; next iteration's x-loads+staging overlap current compute.
// Eliminates the ~14 wave transitions and per-block startup serialization.

#define NHEADS 16
#define DDIM   128
#define CPAIRS 64                        // D/2
#define VEC_PER_S (NHEADS * DDIM / 4)    // 512 float4 per seq position
#define SPB 8                            // seq positions per chunk
#define THREADS VEC_PER_S
#define PERSIST_BLOCKS 296               // 148 SMs x 2 CTAs

template <bool GUARD>
__global__ __launch_bounds__(THREADS, 2)
void rope3d_kernel(const float4* __restrict__ x,
                   const float*  __restrict__ fcos,
                   const float*  __restrict__ fsin,
                   const int*    __restrict__ p_h,
                   const int*    __restrict__ p_w,
                   float4*       __restrict__ out,
                   int s_total, int n_chunks)
{
    const int t = threadIdx.x;

    // Double-buffered: tab[buf][k][p] = {c0,s0,c1,s1} for pair group p
    __shared__ float4 tab[2][SPB][CPAIRS / 2];

    const int h  = *p_h;
    const int w  = *p_w;
    const int hw = h * w;

    const int kk = t >> 6;           // staging: position within chunk (0..7)
    const int cc = t & 63;           // staging: channel pair (0..63)
    const int p  = t & 31;           // compute: pair-group of this float4

    int buf = 0;
    for (int chunk = blockIdx.x; chunk < n_chunks; chunk += PERSIST_BLOCKS, buf ^= 1) {
        const int s0   = chunk * SPB;
        const int base = s0 * VEC_PER_S + t;

        // ---- Front-batch the 8 x-loads for this chunk ----
        float4 v[SPB];
#pragma unroll
        for (int k = 0; k < SPB; ++k) {
            if (!GUARD || (s0 + k < s_total))
                v[k] = x[base + k * VEC_PER_S];
        }

        // ---- Stage cos/sin rows into buffer `buf` ----
        {
            const int s = s0 + kk;
            if (!GUARD || (s < s_total)) {
                const int fi  = s / hw;
                const int rem = s - fi * hw;
                const int hi  = rem / w;
                const int wi  = rem - hi * w;
                const int pos = (cc < 22) ? fi : ((cc < 43) ? hi : wi);
                const float cv = __ldg(&fcos[pos * CPAIRS + cc]);
                const float sv = __ldg(&fsin[pos * CPAIRS + cc]);
                float* dst = &tab[buf][kk][cc >> 1].x;
                dst[(cc & 1) * 2]     = cv;
                dst[(cc & 1) * 2 + 1] = sv;
            }
        }
        __syncthreads();   // buffer `buf` ready; other buffer free for next iter

        // ---- Compute + store ----
#pragma unroll
        for (int k = 0; k < SPB; ++k) {
            if (GUARD && (s0 + k >= s_total)) break;
            const float4 cs = tab[buf][k][p];     // {c0, s0, c1, s1}
            float4 o;
            o.x = fmaf(v[k].x, cs.x, -v[k].y * cs.y);
            o.y = fmaf(v[k].x, cs.y,  v[k].y * cs.x);
            o.z = fmaf(v[k].z, cs.z, -v[k].w * cs.w);
            o.w = fmaf(v[k].z, cs.w,  v[k].w * cs.z);
            out[base + k * VEC_PER_S] = o;
        }
        // No second barrier: next iteration stages into buf^1, which no
        // thread can still be reading (reads of buf^1 ended before the
        // barrier of the PREVIOUS iteration).
    }
}

extern "C" void kernel_launch(void* const* d_in, const int* in_sizes, int n_in,
                              void* d_out, int out_size)
{
    const float4* x    = (const float4*)d_in[0];
    const float*  fcos = (const float*)d_in[1];
    const float*  fsin = (const float*)d_in[2];
    const int* p_h = (const int*)d_in[4];
    const int* p_w = (const int*)d_in[5];
    float4* out = (float4*)d_out;

    const int s_total  = in_sizes[0] / (NHEADS * DDIM);   // 32760
    const int n_chunks = (s_total + SPB - 1) / SPB;       // 4095

    if (s_total % SPB == 0) {
        rope3d_kernel<false><<<PERSIST_BLOCKS, THREADS>>>(
            x, fcos, fsin, p_h, p_w, out, s_total, n_chunks);
    } else {
        rope3d_kernel<true><<<PERSIST_BLOCKS, THREADS>>>(
            x, fcos, fsin, p_h, p_w, out, s_total, n_chunks);
    }
}

// round 13
// speedup vs baseline: 1.0796x; 1.0796x over previous
#include <cuda_runtime.h>
#include <cuda_bf16.h>

// 3D RoPE apply:
//   x: (1, S, N=16, D=128) fp32, S = f*h*w (= 32760)
//   freqs_cos/sin: (1024, 64) fp32, cols [0,22)=F, [22,43)=H, [43,64)=W
//   seq pos s -> (fi, hi, wi); pair c: row = fi (c<22) | hi (c<43) | wi
//   out pair: (xr*cos - xi*sin, xr*sin + xi*cos)
//
// R11: R9 structure (front-batched x loads, packed float4 cos/sin tables,
// default cache policy) at SPB=6 with __launch_bounds__(512,3):
// 48 warps/SM x MLP 6 = 288 in-flight LDG.128 per SM (highest tried),
// regs ~42 -> 3 CTAs/SM fits the register file.

#define NHEADS 16
#define DDIM   128
#define CPAIRS 64                        // D/2
#define VEC_PER_S (NHEADS * DDIM / 4)    // 512 float4 per seq position
#define SPB 6                            // seq positions per block (32760 % 6 == 0)
#define THREADS VEC_PER_S

template <bool GUARD>
__global__ __launch_bounds__(THREADS, 3)
void rope3d_kernel(const float4* __restrict__ x,
                   const float*  __restrict__ fcos,
                   const float*  __restrict__ fsin,
                   const int*    __restrict__ p_h,
                   const int*    __restrict__ p_w,
                   float4*       __restrict__ out,
                   int s_total)
{
    const int s0 = blockIdx.x * SPB;
    const int t  = threadIdx.x;

    // tab[k][p] = {cos[2p], sin[2p], cos[2p+1], sin[2p+1]} for position s0+k
    __shared__ float4 tab[SPB][CPAIRS / 2];

    // ---- Front-batch ALL x loads first (in flight over staging+barrier) ----
    const int base = s0 * VEC_PER_S + t;
    float4 v[SPB];
#pragma unroll
    for (int k = 0; k < SPB; ++k) {
        if (!GUARD || (s0 + k < s_total))
            v[k] = x[base + k * VEC_PER_S];
    }

    // ---- Stage SPB rows of cos/sin, interleaved (384 staging threads) ----
    if (t < SPB * CPAIRS) {
        const int k = t >> 6;        // position within block (0..5)
        const int c = t & 63;        // channel pair (0..63)
        const int s = s0 + k;
        if (!GUARD || (s < s_total)) {
            const int h  = *p_h;
            const int w  = *p_w;
            const int hw = h * w;
            const int fi  = s / hw;
            const int rem = s - fi * hw;
            const int hi  = rem / w;
            const int wi  = rem - hi * w;
            const int pos = (c < 22) ? fi : ((c < 43) ? hi : wi);
            const float cv = __ldg(&fcos[pos * CPAIRS + c]);
            const float sv = __ldg(&fsin[pos * CPAIRS + c]);
            float* dst = &tab[k][c >> 1].x;      // word base of this float4
            dst[(c & 1) * 2]     = cv;
            dst[(c & 1) * 2 + 1] = sv;
        }
    }
    __syncthreads();

    const int p = t & 31;            // pair-group index of this thread's float4

#pragma unroll
    for (int k = 0; k < SPB; ++k) {
        if (GUARD && (s0 + k >= s_total)) break;
        const float4 cs = tab[k][p];             // {c0, s0, c1, s1}
        float4 o;
        o.x = fmaf(v[k].x, cs.x, -v[k].y * cs.y);
        o.y = fmaf(v[k].x, cs.y,  v[k].y * cs.x);
        o.z = fmaf(v[k].z, cs.z, -v[k].w * cs.w);
        o.w = fmaf(v[k].z, cs.w,  v[k].w * cs.z);
        out[base + k * VEC_PER_S] = o;
    }
}

extern "C" void kernel_launch(void* const* d_in, const int* in_sizes, int n_in,
                              void* d_out, int out_size)
{
    const float4* x    = (const float4*)d_in[0];
    const float*  fcos = (const float*)d_in[1];
    const float*  fsin = (const float*)d_in[2];
    const int* p_h = (const int*)d_in[4];
    const int* p_w = (const int*)d_in[5];
    float4* out = (float4*)d_out;

    const int s_total = in_sizes[0] / (NHEADS * DDIM);   // 32760

    if (s_total % SPB == 0) {
        rope3d_kernel<false><<<s_total / SPB, THREADS>>>(
            x, fcos, fsin, p_h, p_w, out, s_total);
    } else {
        rope3d_kernel<true><<<(s_total + SPB - 1) / SPB, THREADS>>>(
            x, fcos, fsin, p_h, p_w, out, s_total);
    }
}

// round 14
// speedup vs baseline: 1.1340x; 1.0503x over previous
#include <cuda_runtime.h>
#include <cuda_bf16.h>

// 3D RoPE apply:
//   x: (1, S, N=16, D=128) fp32, S = f*h*w (= 32760)
//   freqs_cos/sin: (1024, 64) fp32, cols [0,22)=F, [22,43)=H, [43,64)=W
//   seq pos s -> (fi, hi, wi); pair c: row = fi (c<22) | hi (c<43) | wi
//   out pair: (xr*cos - xi*sin, xr*sin + xi*cos)
//
// R13: best-measured structure (R4/R9): SPB=8, 512 threads, 2 CTAs/SM,
// x-loads front-batched before smem staging of packed {c0,s0,c1,s1} tables,
// default cache policy. Micro-fix: h/w scalar loads hoisted to the very top
// so the staging LDGs (barrier-critical path) can issue as early as possible.

#define NHEADS 16
#define DDIM   128
#define CPAIRS 64                        // D/2
#define VEC_PER_S (NHEADS * DDIM / 4)    // 512 float4 per seq position
#define SPB 8                            // seq positions per block
#define THREADS VEC_PER_S

template <bool GUARD>
__global__ __launch_bounds__(THREADS, 2)
void rope3d_kernel(const float4* __restrict__ x,
                   const float*  __restrict__ fcos,
                   const float*  __restrict__ fsin,
                   const int*    __restrict__ p_h,
                   const int*    __restrict__ p_w,
                   float4*       __restrict__ out,
                   int s_total)
{
    // ---- Issue the h/w scalar loads FIRST: staging depends on them and
    // staging gates the block-wide barrier (critical path).
    const int h = __ldg(p_h);
    const int w = __ldg(p_w);

    const int s0 = blockIdx.x * SPB;
    const int t  = threadIdx.x;

    // tab[k][p] = {cos[2p], sin[2p], cos[2p+1], sin[2p+1]} for position s0+k
    __shared__ float4 tab[SPB][CPAIRS / 2];

    // ---- Front-batch ALL 8 x-loads (in flight over staging + barrier) ----
    const int base = s0 * VEC_PER_S + t;
    float4 v[SPB];
#pragma unroll
    for (int k = 0; k < SPB; ++k) {
        if (!GUARD || (s0 + k < s_total))
            v[k] = x[base + k * VEC_PER_S];
    }

    // ---- Stage SPB rows of cos/sin, interleaved (512 threads cover 8x64) ----
    {
        const int k = t >> 6;        // position within block (0..7)
        const int c = t & 63;        // channel pair (0..63)
        const int s = s0 + k;
        if (!GUARD || (s < s_total)) {
            const int hw  = h * w;
            const int fi  = s / hw;
            const int rem = s - fi * hw;
            const int hi  = rem / w;
            const int wi  = rem - hi * w;
            const int pos = (c < 22) ? fi : ((c < 43) ? hi : wi);
            const float cv = __ldg(&fcos[pos * CPAIRS + c]);
            const float sv = __ldg(&fsin[pos * CPAIRS + c]);
            float* dst = &tab[k][c >> 1].x;      // word base of this float4
            dst[(c & 1) * 2]     = cv;
            dst[(c & 1) * 2 + 1] = sv;
        }
    }
    __syncthreads();

    const int p = t & 31;            // pair-group index of this thread's float4

#pragma unroll
    for (int k = 0; k < SPB; ++k) {
        if (GUARD && (s0 + k >= s_total)) break;
        const float4 cs = tab[k][p];             // {c0, s0, c1, s1}
        float4 o;
        o.x = fmaf(v[k].x, cs.x, -v[k].y * cs.y);
        o.y = fmaf(v[k].x, cs.y,  v[k].y * cs.x);
        o.z = fmaf(v[k].z, cs.z, -v[k].w * cs.w);
        o.w = fmaf(v[k].z, cs.w,  v[k].w * cs.z);
        out[base + k * VEC_PER_S] = o;
    }
}

extern "C" void kernel_launch(void* const* d_in, const int* in_sizes, int n_in,
                              void* d_out, int out_size)
{
    const float4* x    = (const float4*)d_in[0];
    const float*  fcos = (const float*)d_in[1];
    const float*  fsin = (const float*)d_in[2];
    const int* p_h = (const int*)d_in[4];
    const int* p_w = (const int*)d_in[5];
    float4* out = (float4*)d_out;

    const int s_total = in_sizes[0] / (NHEADS * DDIM);   // 32760

    if (s_total % SPB == 0) {
        rope3d_kernel<false><<<s_total / SPB, THREADS>>>(
            x, fcos, fsin, p_h, p_w, out, s_total);
    } else {
        rope3d_kernel<true><<<(s_total + SPB - 1) / SPB, THREADS>>>(
            x, fcos, fsin, p_h, p_w, out, s_total);
    }
}